// round 5
// baseline (speedup 1.0000x reference)
#include <cuda_runtime.h>
#include <cuda_fp16.h>

// Problem constants (fixed by the reference)
#define NN      100000      // nodes
#define FF      32          // feats
#define CC      16          // classes
#define EE      1600000     // edges
#define EMB_DIM 6
#define HID     9
#define DEPTH   10
#define DIFF    0.9f
#define ODIFF   0.1f        // 1 - DIFF

#define NF  (NN * FF)
#define NH4 (NN * 4)        // uint4 (8 halfs) per node row of 32 halfs

// ---------------- device scratch (no allocs allowed) ----------------
__device__ int    g_cnt[NN];
__device__ int    g_cur[NN];
__device__ int    g_rowptr[NN + 1];
__device__ int    g_col[EE];
__device__ float  g_invdeg[NN];
__device__ float  g_isd[NN];   // rsqrt(max(deg,1))
__device__ float  g_sqd[NN];   // sqrt(max(deg,1))
__device__ uint4  g_h0[NH4];   // u0 in half (row = 32 halfs = 64B)
__device__ uint4  g_ha[NH4];   // ping
__device__ uint4  g_hb[NH4];   // pong
__device__ float  g_uf[NF];    // fp32 final result of each diffuse phase

__device__ __forceinline__ uint4* hbuf(int sel) {
    return (sel == 0) ? g_h0 : (sel == 1) ? g_ha : g_hb;
}

__device__ __forceinline__ void add8(float* a, uint4 v) {
    const half2* h = reinterpret_cast<const half2*>(&v);
    float2 f0 = __half22float2(h[0]);
    float2 f1 = __half22float2(h[1]);
    float2 f2 = __half22float2(h[2]);
    float2 f3 = __half22float2(h[3]);
    a[0] += f0.x; a[1] += f0.y;
    a[2] += f1.x; a[3] += f1.y;
    a[4] += f2.x; a[5] += f2.y;
    a[6] += f3.x; a[7] += f3.y;
}

__device__ __forceinline__ void unpack8(float* a, uint4 v) {
    const half2* h = reinterpret_cast<const half2*>(&v);
    float2 f0 = __half22float2(h[0]);
    float2 f1 = __half22float2(h[1]);
    float2 f2 = __half22float2(h[2]);
    float2 f3 = __half22float2(h[3]);
    a[0] = f0.x; a[1] = f0.y;
    a[2] = f1.x; a[3] = f1.y;
    a[4] = f2.x; a[5] = f2.y;
    a[6] = f3.x; a[7] = f3.y;
}

__device__ __forceinline__ uint4 pack8(const float* a) {
    uint4 r;
    half2* h = reinterpret_cast<half2*>(&r);
    h[0] = __floats2half2_rn(a[0], a[1]);
    h[1] = __floats2half2_rn(a[2], a[3]);
    h[2] = __floats2half2_rn(a[4], a[5]);
    h[3] = __floats2half2_rn(a[6], a[7]);
    return r;
}

// ---------------- kernels ----------------

__global__ void k_zero() {
    int i = blockIdx.x * blockDim.x + threadIdx.x;
    if (i < NN) { g_cnt[i] = 0; g_cur[i] = 0; }
}

__global__ void k_count(const int* __restrict__ edges) {
    int e = blockIdx.x * blockDim.x + threadIdx.x;
    if (e < EE) {
        int d = edges[EE + e];
        if ((unsigned)d < (unsigned)NN)
            atomicAdd(&g_cnt[d], 1);
    }
}

// single-block exclusive scan of g_cnt -> g_rowptr
__global__ void k_scan() {
    const int T = 1024;
    int tid = threadIdx.x;
    int chunk = (NN + T - 1) / T;                 // 98
    int beg = tid * chunk;
    int end = beg + chunk; if (end > NN) end = NN;
    if (beg > NN) beg = NN;

    int sum = 0;
    for (int i = beg; i < end; i++) sum += g_cnt[i];

    __shared__ int sh[T];
    sh[tid] = sum;
    __syncthreads();
    for (int off = 1; off < T; off <<= 1) {
        int v = (tid >= off) ? sh[tid - off] : 0;
        __syncthreads();
        sh[tid] += v;
        __syncthreads();
    }
    int run = (tid == 0) ? 0 : sh[tid - 1];       // exclusive prefix
    for (int i = beg; i < end; i++) {
        g_rowptr[i] = run;
        run += g_cnt[i];
    }
    if (tid == T - 1) g_rowptr[NN] = run;         // == EE
}

// per-node scalars + u0 = x * rsqrt(deg), stored half2
__global__ void k_prep(const float* __restrict__ x) {
    int idx2 = blockIdx.x * blockDim.x + threadIdx.x;   // half2 index
    if (idx2 >= NF / 2) return;
    int n = idx2 >> 4;
    int c = g_cnt[n];
    float d   = (c > 0) ? (float)c : 1.0f;
    float isd = rsqrtf(d);
    float2 xv = reinterpret_cast<const float2*>(x)[idx2];
    reinterpret_cast<half2*>(g_h0)[idx2] = __floats2half2_rn(xv.x * isd, xv.y * isd);
    if ((idx2 & 15) == 0) {
        g_invdeg[n] = 1.0f / d;
        g_isd[n]    = isd;
        g_sqd[n]    = sqrtf(d);
    }
}

__global__ void k_fill(const int* __restrict__ edges) {
    int e = blockIdx.x * blockDim.x + threadIdx.x;
    if (e < EE) {
        int s = edges[e];
        int d = edges[EE + e];
        if ((unsigned)d < (unsigned)NN && (unsigned)s < (unsigned)NN) {
            int pos = g_rowptr[d] + atomicAdd(&g_cur[d], 1);
            g_col[pos] = s;
        }
    }
}

// one warp per dst node; 8 groups of 4 lanes; group g handles neighbors
// beg+g, beg+g+8, ... Each lane loads uint4 = 8 halfs of the 64B row.
// fp32 accumulate; butterfly-combine groups; sub==0 lanes write.
// OUT_HALF: write half row to hbuf(out_sel); else write fp32 row to g_uf.
template <bool OUT_HALF>
__global__ void __launch_bounds__(256) k_conv(int in_sel, int out_sel) {
    const uint4* __restrict__ u_in = hbuf(in_sel);

    int gwarp = (blockIdx.x * blockDim.x + threadIdx.x) >> 5;
    if (gwarp >= NN) return;
    int lane = threadIdx.x & 31;
    int sub  = lane >> 2;      // neighbor group 0..7
    int fl   = lane & 3;       // uint4 slot within row 0..3

    int beg = g_rowptr[gwarp];
    int end = g_rowptr[gwarp + 1];

    float acc[8] = {0.f, 0.f, 0.f, 0.f, 0.f, 0.f, 0.f, 0.f};
    int j = beg + sub;
    // main: 16 neighbors per iter (2 per group)
    for (; j + 8 < end; j += 16) {
        int s0 = __ldg(&g_col[j]);
        int s1 = __ldg(&g_col[j + 8]);
        uint4 a = __ldg(&u_in[s0 * 4 + fl]);
        uint4 b = __ldg(&u_in[s1 * 4 + fl]);
        add8(acc, a);
        add8(acc, b);
    }
    for (; j < end; j += 8) {
        int s = __ldg(&g_col[j]);
        uint4 a = __ldg(&u_in[s * 4 + fl]);
        add8(acc, a);
    }

    // combine 8 group partials across sub (lanes with equal fl)
    #pragma unroll
    for (int off = 4; off < 32; off <<= 1) {
        #pragma unroll
        for (int k = 0; k < 8; k++)
            acc[k] += __shfl_xor_sync(0xffffffffu, acc[k], off);
    }

    if (sub == 0) {
        float w = DIFF * g_invdeg[gwarp];
        uint4 h0v = __ldg(&g_h0[gwarp * 4 + fl]);
        float h0[8];
        unpack8(h0, h0v);
        float r[8];
        #pragma unroll
        for (int k = 0; k < 8; k++)
            r[k] = fmaf(w, acc[k], ODIFF * h0[k]);
        if (OUT_HALF) {
            hbuf(out_sel)[gwarp * 4 + fl] = pack8(r);
        } else {
            float4* o = reinterpret_cast<float4*>(g_uf);
            o[gwarp * 8 + fl * 2 + 0] = make_float4(r[0], r[1], r[2], r[3]);
            o[gwarp * 8 + fl * 2 + 1] = make_float4(r[4], r[5], r[6], r[7]);
        }
    }
}

// per-(node,feature) MLP elementwise, rescaled in/out of u-space.
// Reads g_uf (fp32), writes new u0 (half) into g_h0. Two feats per thread.
__global__ void k_mlp(const float* __restrict__ emb,
                      const float* __restrict__ W1,
                      const float* __restrict__ b1,
                      const float* __restrict__ W2,
                      const float* __restrict__ b2) {
    __shared__ float sA[HID];           // W1 row 0
    __shared__ float sW2[HID];
    __shared__ float sC[FF][HID];       // b1[j] + sum_d emb[f,d]*W1[1+d,j]
    __shared__ float sB2;

    for (int t = threadIdx.x; t < FF * HID; t += blockDim.x) {
        int f = t / HID, j = t % HID;
        float c = b1[j];
        #pragma unroll
        for (int d = 0; d < EMB_DIM; d++)
            c += emb[f * EMB_DIM + d] * W1[(1 + d) * HID + j];
        sC[f][j] = c;
    }
    if (threadIdx.x < HID) {
        sA[threadIdx.x]  = W1[threadIdx.x];      // row 0
        sW2[threadIdx.x] = W2[threadIdx.x];
    }
    if (threadIdx.x == 0) sB2 = b2[0];
    __syncthreads();

    int idx2 = blockIdx.x * blockDim.x + threadIdx.x;   // half2 index
    if (idx2 >= NF / 2) return;
    int n  = idx2 >> 4;
    int f0 = (idx2 & 15) * 2;
    float sq  = g_sqd[n];
    float isd = g_isd[n];
    float2 tv = reinterpret_cast<const float2*>(g_uf)[idx2];
    float t0 = tv.x * sq, t1 = tv.y * sq;
    float r0 = sB2, r1 = sB2;
    #pragma unroll
    for (int j = 0; j < HID; j++) {
        float h0 = fmaf(sA[j], t0, sC[f0][j]);
        float h1 = fmaf(sA[j], t1, sC[f0 + 1][j]);
        r0 = fmaf(sW2[j], fmaxf(h0, 0.0f), r0);
        r1 = fmaf(sW2[j], fmaxf(h1, 0.0f), r1);
    }
    reinterpret_cast<half2*>(g_h0)[idx2] = __floats2half2_rn(r0 * isd, r1 * isd);
}

// out[n,c] = bout[c] + sum_k (g_uf[n,k]*sqd[n]) * Wout[k,c]
__global__ void k_out(const float* __restrict__ Wout,
                      const float* __restrict__ bout,
                      float* __restrict__ out) {
    __shared__ float sW[FF * CC];
    __shared__ float sb[CC];
    for (int t = threadIdx.x; t < FF * CC; t += blockDim.x) sW[t] = Wout[t];
    if (threadIdx.x < CC) sb[threadIdx.x] = bout[threadIdx.x];
    __syncthreads();

    int tid = blockIdx.x * blockDim.x + threadIdx.x;
    if (tid >= NN * CC) return;
    int n = tid >> 4;
    int c = tid & 15;
    float sd = g_sqd[n];
    float acc = sb[c];
    #pragma unroll
    for (int k = 0; k < FF; k++)
        acc = fmaf(g_uf[n * 32 + k] * sd, sW[k * CC + c], acc);
    out[tid] = acc;
}

// ---------------- launch ----------------

static void diffuse(int gW, int TB) {
    // step 1: u0(half, sel 0) -> ha(1)
    k_conv<true><<<gW, TB>>>(0, 1);
    // steps 2..9: ping-pong ha(1)/hb(2)
    for (int i = 2; i < DEPTH; i++) {
        int in_sel  = (i & 1) ? 2 : 1;
        int out_sel = (i & 1) ? 1 : 2;
        k_conv<true><<<gW, TB>>>(in_sel, out_sel);
    }
    // step 10: in = ha(1) (step 9 wrote sel 1) -> fp32 g_uf
    k_conv<false><<<gW, TB>>>(1, 0 /*unused*/);
}

extern "C" void kernel_launch(void* const* d_in, const int* in_sizes, int n_in,
                              void* d_out, int out_size) {
    const float* x     = (const float*)d_in[0];
    const int*   edges = (const int*)d_in[1];       // int32 per harness dtype contract
    const float* emb   = (const float*)d_in[2];
    const float* W1    = (const float*)d_in[3];
    const float* b1    = (const float*)d_in[4];
    const float* W2    = (const float*)d_in[5];
    const float* b2    = (const float*)d_in[6];
    const float* Wout  = (const float*)d_in[7];
    const float* bout  = (const float*)d_in[8];
    float* out = (float*)d_out;

    const int TB = 256;
    int gN  = (NN + TB - 1) / TB;
    int gE  = (EE + TB - 1) / TB;
    int gH2 = (NF / 2 + TB - 1) / TB;    // half2-element grid
    int gW  = (NN * 32 + TB - 1) / TB;   // warp-per-node grid
    int gNC = (NN * CC + TB - 1) / TB;

    // CSR build + scalars
    k_zero<<<gN, TB>>>();
    k_count<<<gE, TB>>>(edges);
    k_scan<<<1, 1024>>>();
    k_prep<<<gH2, TB>>>(x);
    k_fill<<<gE, TB>>>(edges);

    // diffuse 1 -> g_uf (fp32)
    diffuse(gW, TB);

    // per-element MLP (reads g_uf, writes new half u0 into g_h0)
    k_mlp<<<gH2, TB>>>(emb, W1, b1, W2, b2);

    // diffuse 2 -> g_uf (fp32)
    diffuse(gW, TB);

    // output GEMM
    k_out<<<gNC, TB>>>(Wout, bout, out);
}